// round 2
// baseline (speedup 1.0000x reference)
#include <cuda_runtime.h>
#include <cuda_bf16.h>

// Fixed problem shapes
#define B_   32
#define C_   4
#define P_   (360 * 640)      // 230400
#define L_   5
#define NVEC (P_ / 4)         // 57600 vec4 groups per batch

#define NBLK 64               // blocks per batch (grid.x)
#define TPB  256

#define DELTA_V 1.0f
#define DELTA_D 6.0f

typedef unsigned long long ull;

// ---- static scratch (no allocation allowed) ----
__device__ float    g_psums[B_ * NBLK * L_ * C_];   // per-block partial sums
__device__ int      g_pcnt [B_ * NBLK * L_];        // per-block partial counts
__device__ float4   g_means4[B_][L_ + 1];           // lane 0 = zeros
__device__ float    g_wv    [B_][L_ + 1];           // 1.0 if lane valid else 0.0
__device__ float    g_scalars[4];                   // 0: dist_sum, 1: point_count, 2: var_loss
__device__ int      g_done;                         // dist last-block counter
__device__ unsigned g_tpack[B_ * NVEC];             // 4 labels packed per uint (uint8 each)

// packed f32x2 helpers
__device__ __forceinline__ ull pack2(float a, float b) {
    ull r;
    asm("mov.b64 %0, {%1, %2};" : "=l"(r) : "f"(a), "f"(b));
    return r;
}
__device__ __forceinline__ void unpack2(ull v, float& a, float& b) {
    asm("mov.b64 {%0, %1}, %2;" : "=f"(a), "=f"(b) : "l"(v));
}
__device__ __forceinline__ float sqrt_approx(float x) {
    float r;
    asm("sqrt.approx.f32 %0, %1;" : "=f"(r) : "f"(x));
    return r;
}

// --------------------------------------------------------------------------
// Pass 1: per-(batch,lane) counts + channel sums into per-block partial slots,
// plus uint8 re-pack of targets for pass 2.
__global__ void __launch_bounds__(TPB) accum_kernel(const int* __restrict__ tg,
                                                    const float* __restrict__ emb) {
    const int b = blockIdx.y;
    const int4*   t4 = (const int4*)(tg + (size_t)b * P_);
    const float4* e4 = (const float4*)(emb + (size_t)b * C_ * P_);
    unsigned*     tp = g_tpack + (size_t)b * NVEC;

    ull acc01[L_], acc23[L_];
    int cnt[L_];
#pragma unroll
    for (int l = 0; l < L_; l++) { acc01[l] = 0ULL; acc23[l] = 0ULL; cnt[l] = 0; }

    // predicated packed accumulate: one point (channels across ev0..ev3 comp j)
#define DO_POINT(TT, F0, F1, F2, F3)                                           \
    {                                                                          \
        const int   _t   = (TT);                                               \
        const ull   _p01 = pack2((F0), (F1));                                  \
        const ull   _p23 = pack2((F2), (F3));                                  \
        _Pragma("unroll")                                                      \
        for (int _l = 0; _l < L_; _l++) {                                      \
            asm volatile(                                                      \
                "{\n\t"                                                        \
                ".reg .pred p;\n\t"                                            \
                "setp.eq.s32 p, %3, %4;\n\t"                                   \
                "@p add.rn.f32x2 %0, %0, %5;\n\t"                              \
                "@p add.rn.f32x2 %1, %1, %6;\n\t"                              \
                "@p add.s32 %2, %2, 1;\n\t"                                    \
                "}"                                                            \
                : "+l"(acc01[_l]), "+l"(acc23[_l]), "+r"(cnt[_l])              \
                : "r"(_t), "r"(_l + 1), "l"(_p01), "l"(_p23));                 \
        }                                                                      \
    }

#define DO_GROUP(I)                                                            \
    {                                                                          \
        const int _i = (I);                                                    \
        int4   tv  = t4[_i];                                                   \
        float4 ev0 = e4[_i];                                                   \
        float4 ev1 = e4[(size_t)NVEC + _i];                                    \
        float4 ev2 = e4[(size_t)2 * NVEC + _i];                                \
        float4 ev3 = e4[(size_t)3 * NVEC + _i];                                \
        tp[_i] = (unsigned)tv.x | ((unsigned)tv.y << 8) |                      \
                 ((unsigned)tv.z << 16) | ((unsigned)tv.w << 24);              \
        DO_POINT(tv.x, ev0.x, ev1.x, ev2.x, ev3.x);                            \
        DO_POINT(tv.y, ev0.y, ev1.y, ev2.y, ev3.y);                            \
        DO_POINT(tv.z, ev0.z, ev1.z, ev2.z, ev3.z);                            \
        DO_POINT(tv.w, ev0.w, ev1.w, ev2.w, ev3.w);                            \
    }

    for (int i0 = blockIdx.x * (TPB * 2) + threadIdx.x; i0 < NVEC;
         i0 += NBLK * TPB * 2) {
        const int i1 = i0 + TPB;
        if (i1 < NVEC) {
            DO_GROUP(i0);
            DO_GROUP(i1);
        } else {
            DO_GROUP(i0);
        }
    }
#undef DO_GROUP
#undef DO_POINT

    // unpack accumulators, warp reduce
    float s[L_][C_];
#pragma unroll
    for (int l = 0; l < L_; l++) {
        unpack2(acc01[l], s[l][0], s[l][1]);
        unpack2(acc23[l], s[l][2], s[l][3]);
    }
#pragma unroll
    for (int l = 0; l < L_; l++) {
#pragma unroll
        for (int off = 16; off > 0; off >>= 1) {
            cnt[l] += __shfl_down_sync(0xffffffffu, cnt[l], off);
#pragma unroll
            for (int c = 0; c < C_; c++)
                s[l][c] += __shfl_down_sync(0xffffffffu, s[l][c], off);
        }
    }

    __shared__ float ss[L_ * C_];
    __shared__ int   sc[L_];
    if (threadIdx.x < L_ * C_) ss[threadIdx.x] = 0.0f;
    if (threadIdx.x < L_)      sc[threadIdx.x] = 0;
    __syncthreads();
    if ((threadIdx.x & 31) == 0) {
#pragma unroll
        for (int l = 0; l < L_; l++) {
            atomicAdd(&sc[l], cnt[l]);
#pragma unroll
            for (int c = 0; c < C_; c++) atomicAdd(&ss[l * C_ + c], s[l][c]);
        }
    }
    __syncthreads();

    const int slot = b * NBLK + blockIdx.x;
    if (threadIdx.x < L_ * C_)
        g_psums[(size_t)slot * (L_ * C_) + threadIdx.x] = ss[threadIdx.x];
    if (threadIdx.x < L_)
        g_pcnt[(size_t)slot * L_ + threadIdx.x] = sc[threadIdx.x];
}

// --------------------------------------------------------------------------
// Reduce partials, compute means/validity/point_count and push loss.
// 1024 threads: warp w handles batch w; lane p reduces partials p and p+32.
__global__ void means_kernel() {
    const int lane = threadIdx.x & 31;
    const int b    = threadIdx.x >> 5;

    float s[L_][C_];
    int   cnt[L_];
    {
        const size_t base0 = ((size_t)b * NBLK + lane) * (L_ * C_);
        const size_t base1 = ((size_t)b * NBLK + lane + 32) * (L_ * C_);
        const size_t cb0   = ((size_t)b * NBLK + lane) * L_;
        const size_t cb1   = ((size_t)b * NBLK + lane + 32) * L_;
#pragma unroll
        for (int l = 0; l < L_; l++) {
            cnt[l] = g_pcnt[cb0 + l] + g_pcnt[cb1 + l];
#pragma unroll
            for (int c = 0; c < C_; c++)
                s[l][c] = g_psums[base0 + l * C_ + c] + g_psums[base1 + l * C_ + c];
        }
    }
#pragma unroll
    for (int l = 0; l < L_; l++) {
#pragma unroll
        for (int off = 16; off > 0; off >>= 1) {
            cnt[l] += __shfl_down_sync(0xffffffffu, cnt[l], off);
#pragma unroll
            for (int c = 0; c < C_; c++)
                s[l][c] += __shfl_down_sync(0xffffffffu, s[l][c], off);
        }
    }

    __shared__ float sh_pc[32], sh_var[32], sh_nb[32];

    if (lane == 0) {
        float mean[L_][C_];
        int   vld[L_];
        float pc_local = 0.0f;
#pragma unroll
        for (int l = 0; l < L_; l++) {
            const int cc = cnt[l];
            vld[l] = (cc > 1);
            const float inv = 1.0f / (float)max(cc, 1);
#pragma unroll
            for (int ch = 0; ch < C_; ch++) mean[l][ch] = s[l][ch] * inv;
            g_means4[b][l + 1] = make_float4(mean[l][0], mean[l][1], mean[l][2], mean[l][3]);
            g_wv[b][l + 1] = vld[l] ? 1.0f : 0.0f;
            if (vld[l]) pc_local += (float)cc;
        }
        g_means4[b][0] = make_float4(0.f, 0.f, 0.f, 0.f);
        g_wv[b][0] = 0.0f;

        float psum = 0.0f;
        int npairs = 0;
#pragma unroll
        for (int i = 0; i < L_; i++) {
#pragma unroll
            for (int j = i + 1; j < L_; j++) {
                if (vld[i] && vld[j]) {
                    float sq = 0.0f;
#pragma unroll
                    for (int ch = 0; ch < C_; ch++) {
                        const float d = mean[i][ch] - mean[j][ch];
                        sq = fmaf(d, d, sq);
                    }
                    const float pd = sqrtf(fmaxf(sq, 1e-12f));
                    const float ph = fmaxf(DELTA_D - pd, 0.0f);
                    psum += ph * ph;
                    npairs++;
                }
            }
        }
        sh_var[b] = (npairs > 0) ? psum / (float)npairs : 0.0f;
        sh_nb[b]  = (npairs > 0) ? 1.0f : 0.0f;
        sh_pc[b]  = pc_local;
    }
    __syncthreads();

    if (threadIdx.x < 32) {
        float v = sh_var[threadIdx.x];
        float n = sh_nb[threadIdx.x];
        float p = sh_pc[threadIdx.x];
#pragma unroll
        for (int off = 16; off > 0; off >>= 1) {
            v += __shfl_down_sync(0xffffffffu, v, off);
            n += __shfl_down_sync(0xffffffffu, n, off);
            p += __shfl_down_sync(0xffffffffu, p, off);
        }
        if (threadIdx.x == 0) {
            g_scalars[0] = 0.0f;                       // dist accumulator reset
            g_scalars[1] = p;                          // point_count
            g_scalars[2] = (n > 0.0f) ? v / fmaxf(n, 1.0f) : 0.0f;  // var_loss
            g_done = 0;
        }
    }
}

// --------------------------------------------------------------------------
// Pass 2: pull hinge^2 from packed uint8 labels + embedding; last block
// finalizes the scalar output.
__global__ void __launch_bounds__(TPB) dist_kernel(const float* __restrict__ emb,
                                                   float* __restrict__ out) {
    const int b = blockIdx.y;
    __shared__ float4 sm[L_ + 1];
    __shared__ float  sw[L_ + 1];
    if (threadIdx.x < L_ + 1) {
        sm[threadIdx.x] = g_means4[b][threadIdx.x];
        sw[threadIdx.x] = g_wv[b][threadIdx.x];
    }
    __syncthreads();

    const unsigned* tp = g_tpack + (size_t)b * NVEC;
    const float4*   e4 = (const float4*)(emb + (size_t)b * C_ * P_);

    float local = 0.0f;

#define DO_POINT(TT, F0, F1, F2, F3)                                           \
    {                                                                          \
        const int    _t = (TT);                                                \
        const float4 _m = sm[_t];                                              \
        const float  _w = sw[_t];                                              \
        float _d = (F0) - _m.x;                                                \
        float _q = _d * _d;                                                    \
        _d = (F1) - _m.y; _q = fmaf(_d, _d, _q);                               \
        _d = (F2) - _m.z; _q = fmaf(_d, _d, _q);                               \
        _d = (F3) - _m.w; _q = fmaf(_d, _d, _q);                               \
        const float _dist = sqrt_approx(fmaxf(_q, 1e-12f));                    \
        const float _h = fmaxf(_dist - DELTA_V, 0.0f);                         \
        local = fmaf(_w * _h, _h, local);                                      \
    }

#define DO_GROUP(I)                                                            \
    {                                                                          \
        const int _i = (I);                                                    \
        unsigned _u  = tp[_i];                                                 \
        float4 ev0 = e4[_i];                                                   \
        float4 ev1 = e4[(size_t)NVEC + _i];                                    \
        float4 ev2 = e4[(size_t)2 * NVEC + _i];                                \
        float4 ev3 = e4[(size_t)3 * NVEC + _i];                                \
        DO_POINT((int)(_u & 255u),         ev0.x, ev1.x, ev2.x, ev3.x);        \
        DO_POINT((int)((_u >> 8) & 255u),  ev0.y, ev1.y, ev2.y, ev3.y);        \
        DO_POINT((int)((_u >> 16) & 255u), ev0.z, ev1.z, ev2.z, ev3.z);        \
        DO_POINT((int)(_u >> 24),          ev0.w, ev1.w, ev2.w, ev3.w);        \
    }

    for (int i0 = blockIdx.x * (TPB * 2) + threadIdx.x; i0 < NVEC;
         i0 += NBLK * TPB * 2) {
        const int i1 = i0 + TPB;
        if (i1 < NVEC) {
            DO_GROUP(i0);
            DO_GROUP(i1);
        } else {
            DO_GROUP(i0);
        }
    }
#undef DO_GROUP
#undef DO_POINT

#pragma unroll
    for (int off = 16; off > 0; off >>= 1)
        local += __shfl_down_sync(0xffffffffu, local, off);

    __shared__ float sred;
    if (threadIdx.x == 0) sred = 0.0f;
    __syncthreads();
    if ((threadIdx.x & 31) == 0) atomicAdd(&sred, local);
    __syncthreads();

    if (threadIdx.x == 0) {
        atomicAdd(&g_scalars[0], sred);
        __threadfence();
        const int total = gridDim.x * gridDim.y;
        const int old = atomicAdd(&g_done, 1);
        if (old == total - 1) {
            const float ds = g_scalars[0];
            const float pc = g_scalars[1];
            const float dl = (pc > 0.0f) ? ds / fmaxf(pc, 1.0f) : 0.0f;
            out[0] = dl + g_scalars[2];
        }
    }
}

// --------------------------------------------------------------------------
extern "C" void kernel_launch(void* const* d_in, const int* in_sizes, int n_in,
                              void* d_out, int out_size) {
    const int*   tg  = (const int*)d_in[0];    // targets [32,360,640] int32
    const float* emb = (const float*)d_in[1];  // embedding [32,4,360,640] f32
    float* out = (float*)d_out;

    dim3 grid(NBLK, B_);
    accum_kernel<<<grid, TPB>>>(tg, emb);
    means_kernel<<<1, 1024>>>();
    dist_kernel<<<grid, TPB>>>(emb, out);
}

// round 3
// speedup vs baseline: 1.0278x; 1.0278x over previous
#include <cuda_runtime.h>
#include <cuda_bf16.h>

// Fixed problem shapes
#define B_   32
#define C_   4
#define P_   (360 * 640)      // 230400
#define L_   5
#define NVEC (P_ / 4)         // 57600 vec4 groups per batch

#define ACC_NBLK  16          // accum blocks per batch
#define DIST_NBLK 32          // dist blocks per batch
#define TPB       256

#define DELTA_V 1.0f
#define DELTA_D 6.0f

typedef unsigned long long ull;

// ---- static scratch (no allocation allowed) ----
__device__ float    g_psums[B_ * ACC_NBLK * L_ * C_];  // per-block partial sums
__device__ int      g_pcnt [B_ * ACC_NBLK * L_];       // per-block partial counts
__device__ float4   g_means4[B_][L_ + 1];              // lane 0 = zeros
__device__ float    g_wv    [B_][L_ + 1];              // 1.0 if lane valid else 0.0
__device__ float    g_scalars[4];                      // 0: dist_sum, 1: point_count, 2: var_loss
__device__ int      g_acc_done;                        // accum last-block counter
__device__ int      g_dist_done;                       // dist last-block counter
__device__ unsigned g_tpack[B_ * NVEC];                // 4 labels packed per uint

// packed f32x2 helpers
__device__ __forceinline__ ull pack2(float a, float b) {
    ull r;
    asm("mov.b64 %0, {%1, %2};" : "=l"(r) : "f"(a), "f"(b));
    return r;
}
__device__ __forceinline__ void unpack2(ull v, float& a, float& b) {
    asm("mov.b64 {%0, %1}, %2;" : "=f"(a), "=f"(b) : "l"(v));
}
__device__ __forceinline__ float sqrt_approx(float x) {
    float r;
    asm("sqrt.approx.f32 %0, %1;" : "=f"(r) : "f"(x));
    return r;
}

// --------------------------------------------------------------------------
// Pass 1: per-(batch,lane) counts + channel sums (per-block partials), uint8
// target re-pack, and means + push-loss computed by the last-finishing block.
__global__ void __launch_bounds__(TPB) accum_kernel(const int* __restrict__ tg,
                                                    const float* __restrict__ emb) {
    const int b = blockIdx.y;
    const int4*   t4 = (const int4*)(tg + (size_t)b * P_);
    const float4* e4 = (const float4*)(emb + (size_t)b * C_ * P_);
    unsigned*     tp = g_tpack + (size_t)b * NVEC;

    ull acc01[L_], acc23[L_];
    int cnt[L_];
#pragma unroll
    for (int l = 0; l < L_; l++) { acc01[l] = 0ULL; acc23[l] = 0ULL; cnt[l] = 0; }

#define DO_POINT(TT, F0, F1, F2, F3)                                           \
    {                                                                          \
        const int _t   = (TT);                                                 \
        const ull _p01 = pack2((F0), (F1));                                    \
        const ull _p23 = pack2((F2), (F3));                                    \
        _Pragma("unroll")                                                      \
        for (int _l = 0; _l < L_; _l++) {                                      \
            asm volatile(                                                      \
                "{\n\t"                                                        \
                ".reg .pred p;\n\t"                                            \
                "setp.eq.s32 p, %3, %4;\n\t"                                   \
                "@p add.rn.f32x2 %0, %0, %5;\n\t"                              \
                "@p add.rn.f32x2 %1, %1, %6;\n\t"                              \
                "@p add.s32 %2, %2, 1;\n\t"                                    \
                "}"                                                            \
                : "+l"(acc01[_l]), "+l"(acc23[_l]), "+r"(cnt[_l])              \
                : "r"(_t), "r"(_l + 1), "l"(_p01), "l"(_p23));                 \
        }                                                                      \
    }

#pragma unroll 2
    for (int i = blockIdx.x * TPB + threadIdx.x; i < NVEC; i += ACC_NBLK * TPB) {
        int4   tv  = t4[i];
        float4 ev0 = e4[i];
        float4 ev1 = e4[(size_t)NVEC + i];
        float4 ev2 = e4[(size_t)2 * NVEC + i];
        float4 ev3 = e4[(size_t)3 * NVEC + i];
        tp[i] = (unsigned)tv.x | ((unsigned)tv.y << 8) |
                ((unsigned)tv.z << 16) | ((unsigned)tv.w << 24);
        DO_POINT(tv.x, ev0.x, ev1.x, ev2.x, ev3.x);
        DO_POINT(tv.y, ev0.y, ev1.y, ev2.y, ev3.y);
        DO_POINT(tv.z, ev0.z, ev1.z, ev2.z, ev3.z);
        DO_POINT(tv.w, ev0.w, ev1.w, ev2.w, ev3.w);
    }
#undef DO_POINT

    // unpack + warp reduce
    float s[L_][C_];
#pragma unroll
    for (int l = 0; l < L_; l++) {
        unpack2(acc01[l], s[l][0], s[l][1]);
        unpack2(acc23[l], s[l][2], s[l][3]);
    }
#pragma unroll
    for (int l = 0; l < L_; l++) {
#pragma unroll
        for (int off = 16; off > 0; off >>= 1) {
            cnt[l] += __shfl_down_sync(0xffffffffu, cnt[l], off);
#pragma unroll
            for (int c = 0; c < C_; c++)
                s[l][c] += __shfl_down_sync(0xffffffffu, s[l][c], off);
        }
    }

    __shared__ float ss[L_ * C_];
    __shared__ int   sc[L_];
    if (threadIdx.x < L_ * C_) ss[threadIdx.x] = 0.0f;
    if (threadIdx.x < L_)      sc[threadIdx.x] = 0;
    __syncthreads();
    if ((threadIdx.x & 31) == 0) {
#pragma unroll
        for (int l = 0; l < L_; l++) {
            atomicAdd(&sc[l], cnt[l]);
#pragma unroll
            for (int c = 0; c < C_; c++) atomicAdd(&ss[l * C_ + c], s[l][c]);
        }
    }
    __syncthreads();

    const int slot = b * ACC_NBLK + blockIdx.x;
    if (threadIdx.x < L_ * C_)
        g_psums[(size_t)slot * (L_ * C_) + threadIdx.x] = ss[threadIdx.x];
    if (threadIdx.x < L_)
        g_pcnt[(size_t)slot * L_ + threadIdx.x] = sc[threadIdx.x];

    // ---- last-finishing block computes means + push loss ----
    __shared__ int s_last;
    __syncthreads();
    if (threadIdx.x == 0) {
        __threadfence();
        const int total = gridDim.x * gridDim.y;
        s_last = (atomicAdd(&g_acc_done, 1) == total - 1) ? 1 : 0;
    }
    __syncthreads();
    if (!s_last) return;

    // 256 threads = 8 warps; warp w handles batches w, w+8, w+16, w+24.
    const int lane = threadIdx.x & 31;
    const int wid  = threadIdx.x >> 5;

    __shared__ float sh_pc[8], sh_var[8], sh_nb[8];
    float pc_w = 0.0f, var_w = 0.0f, nb_w = 0.0f;

    for (int bb = wid; bb < B_; bb += 8) {
        float rs[L_][C_];
        int   rc[L_];
        if (lane < ACC_NBLK) {
            const size_t base = ((size_t)bb * ACC_NBLK + lane) * (L_ * C_);
            const size_t cb   = ((size_t)bb * ACC_NBLK + lane) * L_;
#pragma unroll
            for (int l = 0; l < L_; l++) {
                rc[l] = g_pcnt[cb + l];
#pragma unroll
                for (int c = 0; c < C_; c++) rs[l][c] = g_psums[base + l * C_ + c];
            }
        } else {
#pragma unroll
            for (int l = 0; l < L_; l++) {
                rc[l] = 0;
#pragma unroll
                for (int c = 0; c < C_; c++) rs[l][c] = 0.0f;
            }
        }
#pragma unroll
        for (int l = 0; l < L_; l++) {
#pragma unroll
            for (int off = 16; off > 0; off >>= 1) {
                rc[l] += __shfl_down_sync(0xffffffffu, rc[l], off);
#pragma unroll
                for (int c = 0; c < C_; c++)
                    rs[l][c] += __shfl_down_sync(0xffffffffu, rs[l][c], off);
            }
        }
        if (lane == 0) {
            float mean[L_][C_];
            int   vld[L_];
#pragma unroll
            for (int l = 0; l < L_; l++) {
                const int cc = rc[l];
                vld[l] = (cc > 1);
                const float inv = 1.0f / (float)max(cc, 1);
#pragma unroll
                for (int ch = 0; ch < C_; ch++) mean[l][ch] = rs[l][ch] * inv;
                g_means4[bb][l + 1] =
                    make_float4(mean[l][0], mean[l][1], mean[l][2], mean[l][3]);
                g_wv[bb][l + 1] = vld[l] ? 1.0f : 0.0f;
                if (vld[l]) pc_w += (float)cc;
            }
            g_means4[bb][0] = make_float4(0.f, 0.f, 0.f, 0.f);
            g_wv[bb][0] = 0.0f;

            float psum = 0.0f;
            int npairs = 0;
#pragma unroll
            for (int i = 0; i < L_; i++) {
#pragma unroll
                for (int j = i + 1; j < L_; j++) {
                    if (vld[i] && vld[j]) {
                        float sq = 0.0f;
#pragma unroll
                        for (int ch = 0; ch < C_; ch++) {
                            const float d = mean[i][ch] - mean[j][ch];
                            sq = fmaf(d, d, sq);
                        }
                        const float pd = sqrtf(fmaxf(sq, 1e-12f));
                        const float ph = fmaxf(DELTA_D - pd, 0.0f);
                        psum += ph * ph;
                        npairs++;
                    }
                }
            }
            if (npairs > 0) {
                var_w += psum / (float)npairs;
                nb_w  += 1.0f;
            }
        }
    }
    if (lane == 0) { sh_pc[wid] = pc_w; sh_var[wid] = var_w; sh_nb[wid] = nb_w; }
    __syncthreads();
    if (threadIdx.x == 0) {
        float pc = 0.f, var = 0.f, nb = 0.f;
#pragma unroll
        for (int w = 0; w < 8; w++) { pc += sh_pc[w]; var += sh_var[w]; nb += sh_nb[w]; }
        g_scalars[0] = 0.0f;                                        // dist accumulator
        g_scalars[1] = pc;                                          // point_count
        g_scalars[2] = (nb > 0.0f) ? var / fmaxf(nb, 1.0f) : 0.0f;  // var_loss
        g_acc_done = 0;                                             // reset for next replay
        g_dist_done = 0;
        __threadfence();
    }
}

// --------------------------------------------------------------------------
// Pass 2: pull hinge^2 from packed uint8 labels + embedding; last block
// finalizes the scalar output.
__global__ void __launch_bounds__(TPB) dist_kernel(const float* __restrict__ emb,
                                                   float* __restrict__ out) {
    const int b = blockIdx.y;
    __shared__ float4 sm[L_ + 1];
    __shared__ float  sw[L_ + 1];
    if (threadIdx.x < L_ + 1) {
        sm[threadIdx.x] = g_means4[b][threadIdx.x];
        sw[threadIdx.x] = g_wv[b][threadIdx.x];
    }
    __syncthreads();

    const unsigned* tp = g_tpack + (size_t)b * NVEC;
    const float4*   e4 = (const float4*)(emb + (size_t)b * C_ * P_);

    float local = 0.0f;

#define DO_POINT(TT, F0, F1, F2, F3)                                           \
    {                                                                          \
        const int    _t = (TT);                                                \
        const float4 _m = sm[_t];                                              \
        const float  _w = sw[_t];                                              \
        float _d = (F0) - _m.x;                                                \
        float _q = _d * _d;                                                    \
        _d = (F1) - _m.y; _q = fmaf(_d, _d, _q);                               \
        _d = (F2) - _m.z; _q = fmaf(_d, _d, _q);                               \
        _d = (F3) - _m.w; _q = fmaf(_d, _d, _q);                               \
        const float _dist = sqrt_approx(fmaxf(_q, 1e-12f));                    \
        const float _h = fmaxf(_dist - DELTA_V, 0.0f);                         \
        local = fmaf(_w * _h, _h, local);                                      \
    }

#pragma unroll 2
    for (int i = blockIdx.x * TPB + threadIdx.x; i < NVEC; i += DIST_NBLK * TPB) {
        unsigned u = tp[i];
        float4 ev0 = e4[i];
        float4 ev1 = e4[(size_t)NVEC + i];
        float4 ev2 = e4[(size_t)2 * NVEC + i];
        float4 ev3 = e4[(size_t)3 * NVEC + i];
        DO_POINT((int)(u & 255u),         ev0.x, ev1.x, ev2.x, ev3.x);
        DO_POINT((int)((u >> 8) & 255u),  ev0.y, ev1.y, ev2.y, ev3.y);
        DO_POINT((int)((u >> 16) & 255u), ev0.z, ev1.z, ev2.z, ev3.z);
        DO_POINT((int)(u >> 24),          ev0.w, ev1.w, ev2.w, ev3.w);
    }
#undef DO_POINT

#pragma unroll
    for (int off = 16; off > 0; off >>= 1)
        local += __shfl_down_sync(0xffffffffu, local, off);

    __shared__ float sred;
    if (threadIdx.x == 0) sred = 0.0f;
    __syncthreads();
    if ((threadIdx.x & 31) == 0) atomicAdd(&sred, local);
    __syncthreads();

    if (threadIdx.x == 0) {
        atomicAdd(&g_scalars[0], sred);
        __threadfence();
        const int total = gridDim.x * gridDim.y;
        const int old = atomicAdd(&g_dist_done, 1);
        if (old == total - 1) {
            const float ds = g_scalars[0];
            const float pc = g_scalars[1];
            const float dl = (pc > 0.0f) ? ds / fmaxf(pc, 1.0f) : 0.0f;
            out[0] = dl + g_scalars[2];
            g_dist_done = 0;   // reset for next graph replay
        }
    }
}

// --------------------------------------------------------------------------
extern "C" void kernel_launch(void* const* d_in, const int* in_sizes, int n_in,
                              void* d_out, int out_size) {
    const int*   tg  = (const int*)d_in[0];    // targets [32,360,640] int32
    const float* emb = (const float*)d_in[1];  // embedding [32,4,360,640] f32
    float* out = (float*)d_out;

    dim3 agrid(ACC_NBLK, B_);
    dim3 dgrid(DIST_NBLK, B_);
    accum_kernel<<<agrid, TPB>>>(tg, emb);
    dist_kernel<<<dgrid, TPB>>>(emb, out);
}